// round 1
// baseline (speedup 1.0000x reference)
#include <cuda_runtime.h>
#include <cstdint>
#include <cstddef>

#define NMAX 100000
#define EMAX 1600000
#define D 128

// ---------------- static device scratch (no allocations allowed) ----------------
__device__ float g_H[(size_t)NMAX * D];     // GEMM output  (51.2 MB)
__device__ float g_A[(size_t)NMAX * D];     // aggregation output / next layer input
__device__ int   g_cnt[NMAX];
__device__ float g_dis[NMAX];
__device__ int   g_rs[NMAX + 1];
__device__ int   g_cur[NMAX];
__device__ int   g_bsum[256];
__device__ int   g_csrs[EMAX];
__device__ float g_csrw[EMAX];

// ---------------- graph preprocessing ----------------
__global__ void k_zero(int n) {
    int i = blockIdx.x * blockDim.x + threadIdx.x;
    if (i < n) g_cnt[i] = 0;
}

__global__ void k_count(const int* __restrict__ dst, int e) {
    int i = blockIdx.x * blockDim.x + threadIdx.x;
    if (i < e) atomicAdd(&g_cnt[dst[i]], 1);
}

// blockwise exclusive scan (1024 elems/block)
__global__ void k_scan1(int n) {
    __shared__ int sm[1024];
    int i = blockIdx.x * 1024 + threadIdx.x;
    int v = (i < n) ? g_cnt[i] : 0;
    sm[threadIdx.x] = v;
    __syncthreads();
    for (int off = 1; off < 1024; off <<= 1) {
        int t = (threadIdx.x >= (unsigned)off) ? sm[threadIdx.x - off] : 0;
        __syncthreads();
        sm[threadIdx.x] += t;
        __syncthreads();
    }
    if (i < n) g_rs[i] = sm[threadIdx.x] - v;   // exclusive
    if (threadIdx.x == 1023) g_bsum[blockIdx.x] = sm[1023];
}

__global__ void k_scan2(int nb) {
    int run = 0;
    for (int b = 0; b < nb; b++) { int t = g_bsum[b]; g_bsum[b] = run; run += t; }
}

__global__ void k_scan3(int n, int e) {
    int i = blockIdx.x * blockDim.x + threadIdx.x;
    if (i < n) {
        int v = g_rs[i] + g_bsum[i >> 10];
        g_rs[i] = v;
        g_cur[i] = v;
        g_dis[i] = rsqrtf((float)(g_cnt[i] + 1));   // +1 self loop; deg >= 1 always
    }
    if (i == 0) g_rs[n] = e;
}

__global__ void k_scatter(const int* __restrict__ src, const int* __restrict__ dst, int e) {
    int i = blockIdx.x * blockDim.x + threadIdx.x;
    if (i < e) {
        int s = src[i], d = dst[i];
        int p = atomicAdd(&g_cur[d], 1);
        g_csrs[p] = s;
        g_csrw[p] = g_dis[s] * g_dis[d];
    }
}

// ---------------- GEMM: H = X @ W  via 3xTF32 mma.sync ----------------
__device__ __forceinline__ unsigned f2tf32(float f) {
    unsigned u;
    asm("cvt.rna.tf32.f32 %0, %1;" : "=r"(u) : "f"(f));
    return u;
}

__device__ __forceinline__ void mma_tf32(float* c, const unsigned* a, unsigned b0, unsigned b1) {
    asm volatile(
        "mma.sync.aligned.m16n8k8.row.col.f32.tf32.tf32.f32 "
        "{%0,%1,%2,%3}, {%4,%5,%6,%7}, {%8,%9}, {%0,%1,%2,%3};\n"
        : "+f"(c[0]), "+f"(c[1]), "+f"(c[2]), "+f"(c[3])
        : "r"(a[0]), "r"(a[1]), "r"(a[2]), "r"(a[3]), "r"(b0), "r"(b1));
}

#define WPAD 136   // smem row stride (136 % 32 == 8 -> conflict-free B frag loads)

__global__ void __launch_bounds__(256, 1)
k_gemm(const float* __restrict__ X, const float* __restrict__ W,
       float* __restrict__ H, int n) {
    extern __shared__ float smem[];
    float* Wh = smem;                 // [128][WPAD]
    float* Wl = smem + 128 * WPAD;

    int tid = threadIdx.x;
    // load W, split into tf32 hi/lo
    for (int i = tid; i < 128 * 128; i += 256) {
        int r = i >> 7, c = i & 127;
        float w = W[i];
        unsigned hu = f2tf32(w);
        float hf = __uint_as_float(hu);
        unsigned lu = f2tf32(w - hf);
        Wh[r * WPAD + c] = hf;
        Wl[r * WPAD + c] = __uint_as_float(lu);
    }
    __syncthreads();

    int wid = tid >> 5, lane = tid & 31;
    int warp_m = wid >> 1;            // 0..3 -> 32 rows each
    int warp_n = wid & 1;             // 0..1 -> 64 cols each
    int g = lane >> 2, tg = lane & 3;
    int rbase = blockIdx.x * 128 + warp_m * 32;
    int cbase = warp_n * 64;
    int nclamp = n - 1;

    float acc[2][8][4];
#pragma unroll
    for (int mf = 0; mf < 2; mf++)
#pragma unroll
        for (int nt = 0; nt < 8; nt++)
#pragma unroll
            for (int q = 0; q < 4; q++) acc[mf][nt][q] = 0.0f;

    for (int k0 = 0; k0 < 128; k0 += 8) {
        unsigned ah[2][4], al[2][4];
#pragma unroll
        for (int mf = 0; mf < 2; mf++) {
            int r0 = rbase + mf * 16 + g;
            int r1 = r0 + 8;
            if (r0 > nclamp) r0 = nclamp;
            if (r1 > nclamp) r1 = nclamp;
            const float* p0 = X + (size_t)r0 * D + k0 + tg;
            const float* p1 = X + (size_t)r1 * D + k0 + tg;
            float a0 = p0[0], a1 = p1[0], a2 = p0[4], a3 = p1[4];
            ah[mf][0] = f2tf32(a0); al[mf][0] = f2tf32(a0 - __uint_as_float(ah[mf][0]));
            ah[mf][1] = f2tf32(a1); al[mf][1] = f2tf32(a1 - __uint_as_float(ah[mf][1]));
            ah[mf][2] = f2tf32(a2); al[mf][2] = f2tf32(a2 - __uint_as_float(ah[mf][2]));
            ah[mf][3] = f2tf32(a3); al[mf][3] = f2tf32(a3 - __uint_as_float(ah[mf][3]));
        }
#pragma unroll
        for (int nt = 0; nt < 8; nt++) {
            int c = cbase + nt * 8 + g;
            int i0 = (k0 + tg) * WPAD + c;
            int i1 = i0 + 4 * WPAD;
            unsigned b0h = __float_as_uint(Wh[i0]);
            unsigned b1h = __float_as_uint(Wh[i1]);
            unsigned b0l = __float_as_uint(Wl[i0]);
            unsigned b1l = __float_as_uint(Wl[i1]);
#pragma unroll
            for (int mf = 0; mf < 2; mf++) {
                mma_tf32(acc[mf][nt], al[mf], b0h, b1h);  // lo*hi
                mma_tf32(acc[mf][nt], ah[mf], b0l, b1l);  // hi*lo
                mma_tf32(acc[mf][nt], ah[mf], b0h, b1h);  // hi*hi last
            }
        }
    }

    // store
#pragma unroll
    for (int mf = 0; mf < 2; mf++) {
        int r0 = rbase + mf * 16 + g;
        int r1 = r0 + 8;
#pragma unroll
        for (int nt = 0; nt < 8; nt++) {
            int c = cbase + nt * 8 + 2 * tg;
            if (r0 < n) {
                float2 v = make_float2(acc[mf][nt][0], acc[mf][nt][1]);
                *(float2*)(H + (size_t)r0 * D + c) = v;
            }
            if (r1 < n) {
                float2 v = make_float2(acc[mf][nt][2], acc[mf][nt][3]);
                *(float2*)(H + (size_t)r1 * D + c) = v;
            }
        }
    }
}

// ---------------- aggregation: out[v] = sum_e norm_e * H[src_e] + dis[v]^2 * H[v] + b ----------------
__global__ void k_agg(const float* __restrict__ H, const float* __restrict__ bias,
                      float* __restrict__ out, int n) {
    int warp = (blockIdx.x * blockDim.x + threadIdx.x) >> 5;
    int lane = threadIdx.x & 31;
    if (warp >= n) return;
    const float4* H4 = (const float4*)H;

    float dv = g_dis[warp];
    float sw = dv * dv;
    float4 hv = H4[(size_t)warp * 32 + lane];
    float ax = sw * hv.x, ay = sw * hv.y, az = sw * hv.z, aw = sw * hv.w;

    int e = g_rs[warp], end = g_rs[warp + 1];
    for (; e + 4 <= end; e += 4) {
        int s0 = g_csrs[e], s1 = g_csrs[e + 1], s2 = g_csrs[e + 2], s3 = g_csrs[e + 3];
        float w0 = g_csrw[e], w1 = g_csrw[e + 1], w2 = g_csrw[e + 2], w3 = g_csrw[e + 3];
        float4 h0 = H4[(size_t)s0 * 32 + lane];
        float4 h1 = H4[(size_t)s1 * 32 + lane];
        float4 h2 = H4[(size_t)s2 * 32 + lane];
        float4 h3 = H4[(size_t)s3 * 32 + lane];
        ax = fmaf(w0, h0.x, ax); ay = fmaf(w0, h0.y, ay); az = fmaf(w0, h0.z, az); aw = fmaf(w0, h0.w, aw);
        ax = fmaf(w1, h1.x, ax); ay = fmaf(w1, h1.y, ay); az = fmaf(w1, h1.z, az); aw = fmaf(w1, h1.w, aw);
        ax = fmaf(w2, h2.x, ax); ay = fmaf(w2, h2.y, ay); az = fmaf(w2, h2.z, az); aw = fmaf(w2, h2.w, aw);
        ax = fmaf(w3, h3.x, ax); ay = fmaf(w3, h3.y, ay); az = fmaf(w3, h3.z, az); aw = fmaf(w3, h3.w, aw);
    }
    for (; e < end; e++) {
        int s = g_csrs[e];
        float w = g_csrw[e];
        float4 h = H4[(size_t)s * 32 + lane];
        ax = fmaf(w, h.x, ax); ay = fmaf(w, h.y, ay); az = fmaf(w, h.z, az); aw = fmaf(w, h.w, aw);
    }

    float4 b4 = ((const float4*)bias)[lane];
    float4 o = make_float4(ax + b4.x, ay + b4.y, az + b4.z, aw + b4.w);
    ((float4*)out)[(size_t)warp * 32 + lane] = o;
}

// ---------------- launch ----------------
extern "C" void kernel_launch(void* const* d_in, const int* in_sizes, int n_in,
                              void* d_out, int out_size) {
    const float* feat = (const float*)d_in[0];
    const int*   ei   = (const int*)d_in[1];
    const float* W0 = (const float*)d_in[2];
    const float* b0 = (const float*)d_in[3];
    const float* W1 = (const float*)d_in[4];
    const float* b1 = (const float*)d_in[5];
    const float* W2 = (const float*)d_in[6];
    const float* b2 = (const float*)d_in[7];

    int n = in_sizes[0] / D;
    int e = in_sizes[1] / 2;
    if (n > NMAX) n = NMAX;
    if (e > EMAX) e = EMAX;
    const int* src = ei;
    const int* dstp = ei + e;

    float *Hp, *Ap;
    cudaGetSymbolAddress((void**)&Hp, g_H);
    cudaGetSymbolAddress((void**)&Ap, g_A);

    int smem = 2 * 128 * WPAD * 4;   // 139264 B
    cudaFuncSetAttribute(k_gemm, cudaFuncAttributeMaxDynamicSharedMemorySize, smem);

    // preprocessing: degree -> scan -> CSR
    k_zero<<<(n + 255) / 256, 256>>>(n);
    k_count<<<(e + 255) / 256, 256>>>(dstp, e);
    int nb = (n + 1023) / 1024;
    k_scan1<<<nb, 1024>>>(n);
    k_scan2<<<1, 1>>>(nb);
    k_scan3<<<(n + 255) / 256, 256>>>(n, e);
    k_scatter<<<(e + 255) / 256, 256>>>(src, dstp, e);

    int gm = (n + 127) / 128;
    int ga = (int)(((long long)n * 32 + 255) / 256);

    // layer 0
    k_gemm<<<gm, 256, smem>>>(feat, W0, Hp, n);
    k_agg<<<ga, 256>>>(Hp, b0, Ap, n);
    // layer 1
    k_gemm<<<gm, 256, smem>>>(Ap, W1, Hp, n);
    k_agg<<<ga, 256>>>(Hp, b1, Ap, n);
    // layer 2
    k_gemm<<<gm, 256, smem>>>(Ap, W2, Hp, n);
    k_agg<<<ga, 256>>>(Hp, b2, (float*)d_out, n);
}

// round 2
// speedup vs baseline: 1.5889x; 1.5889x over previous
#include <cuda_runtime.h>
#include <cuda_fp16.h>
#include <cuda_bf16.h>
#include <cstdint>
#include <cstddef>

#define NMAX 100000
#define EMAX 1600000
#define D 128

// ---------------- static device scratch (no allocations allowed) ----------------
__device__ __half g_H[(size_t)NMAX * D];    // GEMM output, fp16 (25.6 MB)
__device__ float  g_A[(size_t)NMAX * D];    // aggregation output / next layer input
__device__ int    g_cnt[NMAX];
__device__ float  g_dis[NMAX];
__device__ int    g_rs[NMAX + 1];
__device__ int    g_cur[NMAX];
__device__ int    g_bsum[256];
__device__ int    g_csrs[EMAX];
__device__ float  g_csrw[EMAX];

// ---------------- graph preprocessing ----------------
__global__ void k_zero(int n) {
    int i = blockIdx.x * blockDim.x + threadIdx.x;
    if (i < n) g_cnt[i] = 0;
}

__global__ void k_count(const int* __restrict__ dst, int e) {
    int i = blockIdx.x * blockDim.x + threadIdx.x;
    if (i < e) atomicAdd(&g_cnt[dst[i]], 1);
}

// blockwise exclusive scan (1024 elems/block)
__global__ void k_scan1(int n) {
    __shared__ int sm[1024];
    int i = blockIdx.x * 1024 + threadIdx.x;
    int v = (i < n) ? g_cnt[i] : 0;
    sm[threadIdx.x] = v;
    __syncthreads();
    for (int off = 1; off < 1024; off <<= 1) {
        int t = (threadIdx.x >= (unsigned)off) ? sm[threadIdx.x - off] : 0;
        __syncthreads();
        sm[threadIdx.x] += t;
        __syncthreads();
    }
    if (i < n) g_rs[i] = sm[threadIdx.x] - v;   // exclusive within block
    if (threadIdx.x == 1023) g_bsum[blockIdx.x] = sm[1023];
}

// fused: add prior block sums + finalize rowstarts + dis
__global__ void k_scan3(int n, int e) {
    int b = blockIdx.x;
    int pre = 0;
    for (int j = 0; j < b; j++) pre += g_bsum[j];
    int i = b * 1024 + threadIdx.x;
    if (i < n) {
        int v = g_rs[i] + pre;
        g_rs[i] = v;
        g_cur[i] = v;
        g_dis[i] = rsqrtf((float)(g_cnt[i] + 1));   // +1 self loop
    }
    if (i == 0) g_rs[n] = e;
}

__global__ void k_scatter(const int* __restrict__ src, const int* __restrict__ dst, int e) {
    int i = blockIdx.x * blockDim.x + threadIdx.x;
    if (i < e) {
        int s = src[i], d = dst[i];
        int p = atomicAdd(&g_cur[d], 1);
        g_csrs[p] = s;
        g_csrw[p] = g_dis[s] * g_dis[d];
    }
}

// ---------------- GEMM: H = X @ W  via split-bf16 (hi+lo) mma.sync m16n8k16 ----------------
__device__ __forceinline__ void mma_bf16(float* c, const unsigned* a, unsigned b0, unsigned b1) {
    asm volatile(
        "mma.sync.aligned.m16n8k16.row.col.f32.bf16.bf16.f32 "
        "{%0,%1,%2,%3}, {%4,%5,%6,%7}, {%8,%9}, {%0,%1,%2,%3};\n"
        : "+f"(c[0]), "+f"(c[1]), "+f"(c[2]), "+f"(c[3])
        : "r"(a[0]), "r"(a[1]), "r"(a[2]), "r"(a[3]), "r"(b0), "r"(b1));
}

__device__ __forceinline__ void split_pack(float x, float y, unsigned& hi, unsigned& lo) {
    __nv_bfloat162 h = __floats2bfloat162_rn(x, y);        // low half = x
    float hx = __bfloat162float(h.x), hy = __bfloat162float(h.y);
    __nv_bfloat162 l = __floats2bfloat162_rn(x - hx, y - hy);
    hi = *(unsigned*)&h;
    lo = *(unsigned*)&l;
}

#define BSTR 136   // smem stride in uint32; bank = (8*row + col)%32 -> conflict-free frag loads

__global__ void __launch_bounds__(256)
k_gemm(const float* __restrict__ X, const float* __restrict__ W,
       __half* __restrict__ H, int n) {
    extern __shared__ unsigned smem[];
    unsigned* Bh = smem;               // [64][BSTR]  packed bf16x2 pairs over k
    unsigned* Bl = smem + 64 * BSTR;

    int tid = threadIdx.x;
    // load W (row-major [k][c]), split to bf16 hi/lo, pack pairs (k=2j, 2j+1)
    for (int i = tid; i < 64 * 128; i += 256) {
        int j = i >> 7, c = i & 127;
        float w0 = W[(2 * j) * 128 + c];
        float w1 = W[(2 * j + 1) * 128 + c];
        unsigned hi, lo;
        split_pack(w0, w1, hi, lo);
        Bh[j * BSTR + c] = hi;
        Bl[j * BSTR + c] = lo;
    }
    __syncthreads();

    int wid = tid >> 5, lane = tid & 31;
    int warp_m = wid >> 1;            // 0..3 -> 32 rows each
    int warp_n = wid & 1;             // 0..1 -> 64 cols each
    int g = lane >> 2, tg = lane & 3;
    int rbase = blockIdx.x * 128 + warp_m * 32;
    int cbase = warp_n * 64;
    int nclamp = n - 1;

    float acc[2][8][4];
#pragma unroll
    for (int mf = 0; mf < 2; mf++)
#pragma unroll
        for (int nt = 0; nt < 8; nt++)
#pragma unroll
            for (int q = 0; q < 4; q++) acc[mf][nt][q] = 0.0f;

    for (int k0 = 0; k0 < 128; k0 += 16) {
        unsigned ah[2][4], al[2][4];
#pragma unroll
        for (int mf = 0; mf < 2; mf++) {
            int r0 = rbase + mf * 16 + g;
            int r1 = r0 + 8;
            if (r0 > nclamp) r0 = nclamp;
            if (r1 > nclamp) r1 = nclamp;
            const float* p0 = X + (size_t)r0 * D + k0 + 2 * tg;
            const float* p1 = X + (size_t)r1 * D + k0 + 2 * tg;
            float2 f00 = *(const float2*)(p0);        // row g,   k pair
            float2 f01 = *(const float2*)(p0 + 8);    // row g,   k+8 pair
            float2 f10 = *(const float2*)(p1);        // row g+8, k pair
            float2 f11 = *(const float2*)(p1 + 8);    // row g+8, k+8 pair
            split_pack(f00.x, f00.y, ah[mf][0], al[mf][0]);
            split_pack(f10.x, f10.y, ah[mf][1], al[mf][1]);
            split_pack(f01.x, f01.y, ah[mf][2], al[mf][2]);
            split_pack(f11.x, f11.y, ah[mf][3], al[mf][3]);
        }
#pragma unroll
        for (int nt = 0; nt < 8; nt++) {
            int c = cbase + nt * 8 + g;
            int i0 = (k0 / 2 + tg) * BSTR + c;
            int i1 = i0 + 4 * BSTR;
            unsigned b0h = Bh[i0], b1h = Bh[i1];
            unsigned b0l = Bl[i0], b1l = Bl[i1];
#pragma unroll
            for (int mf = 0; mf < 2; mf++) {
                mma_bf16(acc[mf][nt], ah[mf], b0l, b1l);  // hi*lo
                mma_bf16(acc[mf][nt], al[mf], b0h, b1h);  // lo*hi
                mma_bf16(acc[mf][nt], ah[mf], b0h, b1h);  // hi*hi
            }
        }
    }

    // store fp16
#pragma unroll
    for (int mf = 0; mf < 2; mf++) {
        int r0 = rbase + mf * 16 + g;
        int r1 = r0 + 8;
#pragma unroll
        for (int nt = 0; nt < 8; nt++) {
            int c = cbase + nt * 8 + 2 * tg;
            if (r0 < n) {
                __half2 v = __floats2half2_rn(acc[mf][nt][0], acc[mf][nt][1]);
                *(__half2*)(H + (size_t)r0 * D + c) = v;
            }
            if (r1 < n) {
                __half2 v = __floats2half2_rn(acc[mf][nt][2], acc[mf][nt][3]);
                *(__half2*)(H + (size_t)r1 * D + c) = v;
            }
        }
    }
}

// ---------------- aggregation: out[v] = sum_e norm_e * H[src_e] + dis[v]^2 * H[v] + b ----------------
__global__ void k_agg(const __half* __restrict__ Hh, const float* __restrict__ bias,
                      float* __restrict__ out, int n) {
    int warp = (blockIdx.x * blockDim.x + threadIdx.x) >> 5;
    int lane = threadIdx.x & 31;
    if (warp >= n) return;
    const uint2* H2 = (const uint2*)Hh;   // 4 halves per lane; row stride = 32 uint2

    float dv = g_dis[warp];
    float sw = dv * dv;

    uint2 uv = H2[(size_t)warp * 32 + lane];
    float2 v0 = __half22float2(*(__half2*)&uv.x);
    float2 v1 = __half22float2(*(__half2*)&uv.y);
    float ax = sw * v0.x, ay = sw * v0.y, az = sw * v1.x, aw = sw * v1.y;

    int e = g_rs[warp], end = g_rs[warp + 1];
    for (; e + 4 <= end; e += 4) {
        int s0 = g_csrs[e], s1 = g_csrs[e + 1], s2 = g_csrs[e + 2], s3 = g_csrs[e + 3];
        float w0 = g_csrw[e], w1 = g_csrw[e + 1], w2 = g_csrw[e + 2], w3 = g_csrw[e + 3];
        uint2 u0 = H2[(size_t)s0 * 32 + lane];
        uint2 u1 = H2[(size_t)s1 * 32 + lane];
        uint2 u2 = H2[(size_t)s2 * 32 + lane];
        uint2 u3 = H2[(size_t)s3 * 32 + lane];
        float2 a0 = __half22float2(*(__half2*)&u0.x), b0 = __half22float2(*(__half2*)&u0.y);
        float2 a1 = __half22float2(*(__half2*)&u1.x), b1 = __half22float2(*(__half2*)&u1.y);
        float2 a2 = __half22float2(*(__half2*)&u2.x), b2 = __half22float2(*(__half2*)&u2.y);
        float2 a3 = __half22float2(*(__half2*)&u3.x), b3 = __half22float2(*(__half2*)&u3.y);
        ax = fmaf(w0, a0.x, ax); ay = fmaf(w0, a0.y, ay); az = fmaf(w0, b0.x, az); aw = fmaf(w0, b0.y, aw);
        ax = fmaf(w1, a1.x, ax); ay = fmaf(w1, a1.y, ay); az = fmaf(w1, b1.x, az); aw = fmaf(w1, b1.y, aw);
        ax = fmaf(w2, a2.x, ax); ay = fmaf(w2, a2.y, ay); az = fmaf(w2, b2.x, az); aw = fmaf(w2, b2.y, aw);
        ax = fmaf(w3, a3.x, ax); ay = fmaf(w3, a3.y, ay); az = fmaf(w3, b3.x, az); aw = fmaf(w3, b3.y, aw);
    }
    for (; e < end; e++) {
        int s = g_csrs[e];
        float w = g_csrw[e];
        uint2 u = H2[(size_t)s * 32 + lane];
        float2 a = __half22float2(*(__half2*)&u.x), b = __half22float2(*(__half2*)&u.y);
        ax = fmaf(w, a.x, ax); ay = fmaf(w, a.y, ay); az = fmaf(w, b.x, az); aw = fmaf(w, b.y, aw);
    }

    float4 b4 = ((const float4*)bias)[lane];
    float4 o = make_float4(ax + b4.x, ay + b4.y, az + b4.z, aw + b4.w);
    ((float4*)out)[(size_t)warp * 32 + lane] = o;
}

// ---------------- launch ----------------
extern "C" void kernel_launch(void* const* d_in, const int* in_sizes, int n_in,
                              void* d_out, int out_size) {
    const float* feat = (const float*)d_in[0];
    const int*   ei   = (const int*)d_in[1];
    const float* W0 = (const float*)d_in[2];
    const float* b0 = (const float*)d_in[3];
    const float* W1 = (const float*)d_in[4];
    const float* b1 = (const float*)d_in[5];
    const float* W2 = (const float*)d_in[6];
    const float* b2 = (const float*)d_in[7];

    int n = in_sizes[0] / D;
    int e = in_sizes[1] / 2;
    if (n > NMAX) n = NMAX;
    if (e > EMAX) e = EMAX;
    const int* src = ei;
    const int* dstp = ei + e;

    __half* Hp;
    float*  Ap;
    cudaGetSymbolAddress((void**)&Hp, g_H);
    cudaGetSymbolAddress((void**)&Ap, g_A);

    int smem = 2 * 64 * BSTR * 4;   // 69632 B
    cudaFuncSetAttribute(k_gemm, cudaFuncAttributeMaxDynamicSharedMemorySize, smem);

    // preprocessing: degree -> scan -> CSR  (5 launches; launch #5 = first gemm for ncu)
    k_zero<<<(n + 255) / 256, 256>>>(n);
    k_count<<<(e + 255) / 256, 256>>>(dstp, e);
    int nb = (n + 1023) / 1024;
    k_scan1<<<nb, 1024>>>(n);
    k_scan3<<<nb, 1024>>>(n, e);
    k_scatter<<<(e + 255) / 256, 256>>>(src, dstp, e);

    int gm = (n + 127) / 128;
    int ga = (int)(((long long)n * 32 + 255) / 256);

    // layer 0
    k_gemm<<<gm, 256, smem>>>(feat, W0, Hp, n);
    k_agg<<<ga, 256>>>(Hp, b0, Ap, n);
    // layer 1
    k_gemm<<<gm, 256, smem>>>(Ap, W1, Hp, n);
    k_agg<<<ga, 256>>>(Hp, b1, Ap, n);
    // layer 2
    k_gemm<<<gm, 256, smem>>>(Ap, W2, Hp, n);
    k_agg<<<ga, 256>>>(Hp, b2, (float*)d_out, n);
}

// round 4
// speedup vs baseline: 1.7339x; 1.0912x over previous
#include <cuda_runtime.h>
#include <cuda_fp16.h>
#include <cstdint>
#include <cstddef>

#define NMAX 100000
#define EMAX 1600000
#define D 128

// ---------------- static device scratch ----------------
__device__ __half g_H[(size_t)NMAX * D];    // GEMM output, fp16 (25.6 MB)
__device__ float  g_A[(size_t)NMAX * D];    // aggregation output / next layer input
__device__ int    g_cnt[NMAX];
__device__ float  g_dis[NMAX];
__device__ int    g_rs[NMAX + 1];
__device__ int    g_cur[NMAX];
__device__ int    g_bsum[256];
__device__ int    g_csrs[EMAX];
__device__ float  g_csrw[EMAX];

// ---------------- graph preprocessing ----------------
__global__ void k_zero(int n) {
    int i = blockIdx.x * blockDim.x + threadIdx.x;
    if (i < n) g_cnt[i] = 0;
}

__global__ void k_count(const int* __restrict__ dst, int e) {
    int i = blockIdx.x * blockDim.x + threadIdx.x;
    if (i < e) atomicAdd(&g_cnt[dst[i]], 1);
}

__global__ void k_scan1(int n) {
    __shared__ int sm[1024];
    int i = blockIdx.x * 1024 + threadIdx.x;
    int v = (i < n) ? g_cnt[i] : 0;
    sm[threadIdx.x] = v;
    __syncthreads();
    for (int off = 1; off < 1024; off <<= 1) {
        int t = (threadIdx.x >= (unsigned)off) ? sm[threadIdx.x - off] : 0;
        __syncthreads();
        sm[threadIdx.x] += t;
        __syncthreads();
    }
    if (i < n) g_rs[i] = sm[threadIdx.x] - v;   // exclusive within block
    if (threadIdx.x == 1023) g_bsum[blockIdx.x] = sm[1023];
}

__global__ void k_scan3(int n, int e) {
    int b = blockIdx.x;
    int pre = 0;
    for (int j = 0; j < b; j++) pre += g_bsum[j];
    int i = b * 1024 + threadIdx.x;
    if (i < n) {
        int v = g_rs[i] + pre;
        g_rs[i] = v;
        g_cur[i] = v;
        g_dis[i] = rsqrtf((float)(g_cnt[i] + 1));   // +1 self loop
    }
    if (i == 0) g_rs[n] = e;
}

__global__ void k_scatter(const int* __restrict__ src, const int* __restrict__ dst, int e) {
    int i = blockIdx.x * blockDim.x + threadIdx.x;
    if (i < e) {
        int s = src[i], d = dst[i];
        int p = atomicAdd(&g_cur[d], 1);
        g_csrs[p] = s;
        g_csrw[p] = g_dis[s] * g_dis[d];
    }
}

// ---------------- GEMM: H = X @ W  via fp16 2-pass split (A=hi+lo, W=fp16) ----------------
__device__ __forceinline__ void mma_f16(float* c, const unsigned* a, unsigned b0, unsigned b1) {
    asm volatile(
        "mma.sync.aligned.m16n8k16.row.col.f32.f16.f16.f32 "
        "{%0,%1,%2,%3}, {%4,%5,%6,%7}, {%8,%9}, {%0,%1,%2,%3};\n"
        : "+f"(c[0]), "+f"(c[1]), "+f"(c[2]), "+f"(c[3])
        : "r"(a[0]), "r"(a[1]), "r"(a[2]), "r"(a[3]), "r"(b0), "r"(b1));
}

__device__ __forceinline__ void split_pack_h(float x, float y, unsigned& hi, unsigned& lo) {
    __half2 h = __floats2half2_rn(x, y);
    float2 hf = __half22float2(h);
    __half2 l = __floats2half2_rn(x - hf.x, y - hf.y);
    hi = *(unsigned*)&h;
    lo = *(unsigned*)&l;
}

#define BSTR 136   // smem stride in uint32 -> conflict-free frag loads

__global__ void __launch_bounds__(256)
k_gemm(const float* __restrict__ X, const float* __restrict__ W,
       __half* __restrict__ H, int n) {
    __shared__ unsigned Bh[64 * BSTR];   // packed half2 pairs over k (34.8 KB)

    int tid = threadIdx.x;
    // load W (row-major [k][c]) as fp16 pairs (k=2j, 2j+1)
    for (int i = tid; i < 64 * 128; i += 256) {
        int j = i >> 7, c = i & 127;
        float w0 = W[(2 * j) * 128 + c];
        float w1 = W[(2 * j + 1) * 128 + c];
        __half2 h = __floats2half2_rn(w0, w1);
        Bh[j * BSTR + c] = *(unsigned*)&h;
    }
    __syncthreads();

    int wid = tid >> 5, lane = tid & 31;
    int warp_m = wid >> 1;            // 0..3 -> 32 rows each
    int warp_n = wid & 1;             // 0..1 -> 64 cols each
    int g = lane >> 2, tg = lane & 3;
    int rbase = blockIdx.x * 128 + warp_m * 32;
    int cbase = warp_n * 64;
    int nclamp = n - 1;

    float acc[2][8][4];
#pragma unroll
    for (int mf = 0; mf < 2; mf++)
#pragma unroll
        for (int nt = 0; nt < 8; nt++)
#pragma unroll
            for (int q = 0; q < 4; q++) acc[mf][nt][q] = 0.0f;

    for (int k0 = 0; k0 < 128; k0 += 16) {
        unsigned ah[2][4], al[2][4];
#pragma unroll
        for (int mf = 0; mf < 2; mf++) {
            int r0 = rbase + mf * 16 + g;
            int r1 = r0 + 8;
            if (r0 > nclamp) r0 = nclamp;
            if (r1 > nclamp) r1 = nclamp;
            const float* p0 = X + (size_t)r0 * D + k0 + 2 * tg;
            const float* p1 = X + (size_t)r1 * D + k0 + 2 * tg;
            float2 f00 = *(const float2*)(p0);
            float2 f01 = *(const float2*)(p0 + 8);
            float2 f10 = *(const float2*)(p1);
            float2 f11 = *(const float2*)(p1 + 8);
            split_pack_h(f00.x, f00.y, ah[mf][0], al[mf][0]);
            split_pack_h(f10.x, f10.y, ah[mf][1], al[mf][1]);
            split_pack_h(f01.x, f01.y, ah[mf][2], al[mf][2]);
            split_pack_h(f11.x, f11.y, ah[mf][3], al[mf][3]);
        }
#pragma unroll
        for (int nt = 0; nt < 8; nt++) {
            int c = cbase + nt * 8 + g;
            int i0 = (k0 / 2 + tg) * BSTR + c;
            int i1 = i0 + 4 * BSTR;
            unsigned b0 = Bh[i0], b1 = Bh[i1];
#pragma unroll
            for (int mf = 0; mf < 2; mf++) {
                mma_f16(acc[mf][nt], al[mf], b0, b1);  // lo*W
                mma_f16(acc[mf][nt], ah[mf], b0, b1);  // hi*W
            }
        }
    }

    // store fp16
#pragma unroll
    for (int mf = 0; mf < 2; mf++) {
        int r0 = rbase + mf * 16 + g;
        int r1 = r0 + 8;
#pragma unroll
        for (int nt = 0; nt < 8; nt++) {
            int c = cbase + nt * 8 + 2 * tg;
            if (r0 < n) {
                __half2 v = __floats2half2_rn(acc[mf][nt][0], acc[mf][nt][1]);
                *(__half2*)(H + (size_t)r0 * D + c) = v;
            }
            if (r1 < n) {
                __half2 v = __floats2half2_rn(acc[mf][nt][2], acc[mf][nt][3]);
                *(__half2*)(H + (size_t)r1 * D + c) = v;
            }
        }
    }
}

// ---------------- aggregation ----------------
__global__ void k_agg(const __half* __restrict__ Hh, const float* __restrict__ bias,
                      float* __restrict__ out, int n) {
    int warp = (blockIdx.x * blockDim.x + threadIdx.x) >> 5;
    int lane = threadIdx.x & 31;
    if (warp >= n) return;
    const uint2* H2 = (const uint2*)Hh;   // 4 halves per lane; row stride = 32 uint2

    float dv = g_dis[warp];
    float sw = dv * dv;

    uint2 uv = H2[(size_t)warp * 32 + lane];
    float2 v0 = __half22float2(*(__half2*)&uv.x);
    float2 v1 = __half22float2(*(__half2*)&uv.y);
    float ax = sw * v0.x, ay = sw * v0.y, az = sw * v1.x, aw = sw * v1.y;

    int e = g_rs[warp], end = g_rs[warp + 1];
    for (; e + 8 <= end; e += 8) {
        int   s[8];
        float w[8];
        uint2 u[8];
#pragma unroll
        for (int j = 0; j < 8; j++) { s[j] = g_csrs[e + j]; w[j] = g_csrw[e + j]; }
#pragma unroll
        for (int j = 0; j < 8; j++) u[j] = H2[(size_t)s[j] * 32 + lane];
#pragma unroll
        for (int j = 0; j < 8; j++) {
            float2 a = __half22float2(*(__half2*)&u[j].x);
            float2 b = __half22float2(*(__half2*)&u[j].y);
            ax = fmaf(w[j], a.x, ax); ay = fmaf(w[j], a.y, ay);
            az = fmaf(w[j], b.x, az); aw = fmaf(w[j], b.y, aw);
        }
    }
    for (; e + 4 <= end; e += 4) {
        int   s[4];
        float w[4];
        uint2 u[4];
#pragma unroll
        for (int j = 0; j < 4; j++) { s[j] = g_csrs[e + j]; w[j] = g_csrw[e + j]; }
#pragma unroll
        for (int j = 0; j < 4; j++) u[j] = H2[(size_t)s[j] * 32 + lane];
#pragma unroll
        for (int j = 0; j < 4; j++) {
            float2 a = __half22float2(*(__half2*)&u[j].x);
            float2 b = __half22float2(*(__half2*)&u[j].y);
            ax = fmaf(w[j], a.x, ax); ay = fmaf(w[j], a.y, ay);
            az = fmaf(w[j], b.x, az); aw = fmaf(w[j], b.y, aw);
        }
    }
    for (; e < end; e++) {
        int s0 = g_csrs[e];
        float w0 = g_csrw[e];
        uint2 u = H2[(size_t)s0 * 32 + lane];
        float2 a = __half22float2(*(__half2*)&u.x), b = __half22float2(*(__half2*)&u.y);
        ax = fmaf(w0, a.x, ax); ay = fmaf(w0, a.y, ay); az = fmaf(w0, b.x, az); aw = fmaf(w0, b.y, aw);
    }

    float4 b4 = ((const float4*)bias)[lane];
    float4 o = make_float4(ax + b4.x, ay + b4.y, az + b4.z, aw + b4.w);
    ((float4*)out)[(size_t)warp * 32 + lane] = o;
}

// ---------------- launch (single stream, graph-capture safe) ----------------
extern "C" void kernel_launch(void* const* d_in, const int* in_sizes, int n_in,
                              void* d_out, int out_size) {
    const float* feat = (const float*)d_in[0];
    const int*   ei   = (const int*)d_in[1];
    const float* W0 = (const float*)d_in[2];
    const float* b0 = (const float*)d_in[3];
    const float* W1 = (const float*)d_in[4];
    const float* b1 = (const float*)d_in[5];
    const float* W2 = (const float*)d_in[6];
    const float* b2 = (const float*)d_in[7];

    int n = in_sizes[0] / D;
    int e = in_sizes[1] / 2;
    if (n > NMAX) n = NMAX;
    if (e > EMAX) e = EMAX;
    const int* src = ei;
    const int* dstp = ei + e;

    __half* Hp;
    float*  Ap;
    cudaGetSymbolAddress((void**)&Hp, g_H);
    cudaGetSymbolAddress((void**)&Ap, g_A);

    int nb = (n + 1023) / 1024;
    int gm = (n + 127) / 128;
    int ga = (int)(((long long)n * 32 + 255) / 256);

    // preprocessing: degree -> scan -> CSR
    k_zero<<<(n + 255) / 256, 256>>>(n);
    k_count<<<(e + 255) / 256, 256>>>(dstp, e);
    k_scan1<<<nb, 1024>>>(n);
    k_scan3<<<nb, 1024>>>(n, e);
    k_scatter<<<(e + 255) / 256, 256>>>(src, dstp, e);

    // layer 0   (launch index 5 = gemm0 -> ncu -s 5 lands here)
    k_gemm<<<gm, 256>>>(feat, W0, Hp, n);
    k_agg<<<ga, 256>>>(Hp, b0, Ap, n);
    // layer 1
    k_gemm<<<gm, 256>>>(Ap, W1, Hp, n);
    k_agg<<<ga, 256>>>(Hp, b1, Ap, n);
    // layer 2
    k_gemm<<<gm, 256>>>(Ap, W2, Hp, n);
    k_agg<<<ga, 256>>>(Hp, b2, (float*)d_out, n);
}

// round 6
// speedup vs baseline: 1.8159x; 1.0473x over previous
#include <cuda_runtime.h>
#include <cuda_fp16.h>
#include <cstdint>
#include <cstddef>

#define NMAX 100000
#define EMAX 1600000
#define D 128

// ---------------- static device scratch ----------------
__device__ __half g_H[(size_t)NMAX * D];    // GEMM output, fp16 (25.6 MB)
__device__ __half g_A[(size_t)NMAX * D];    // aggregation output, fp16 (25.6 MB)
__device__ int    g_cnt[NMAX];
__device__ float  g_dis[NMAX];
__device__ int    g_rs[NMAX + 1];
__device__ int    g_cur[NMAX];
__device__ int    g_bsum[256];
__device__ int    g_csrs[EMAX];
__device__ float  g_csrw[EMAX];

// ---------------- graph preprocessing ----------------
__global__ void k_zero(int n) {
    int i = blockIdx.x * blockDim.x + threadIdx.x;
    if (i < n) g_cnt[i] = 0;
}

__global__ void k_count(const int* __restrict__ dst, int e) {
    int i = blockIdx.x * blockDim.x + threadIdx.x;
    if (i < e) atomicAdd(&g_cnt[dst[i]], 1);
}

__global__ void k_scan1(int n) {
    __shared__ int sm[1024];
    int i = blockIdx.x * 1024 + threadIdx.x;
    int v = (i < n) ? g_cnt[i] : 0;
    sm[threadIdx.x] = v;
    __syncthreads();
    for (int off = 1; off < 1024; off <<= 1) {
        int t = (threadIdx.x >= (unsigned)off) ? sm[threadIdx.x - off] : 0;
        __syncthreads();
        sm[threadIdx.x] += t;
        __syncthreads();
    }
    if (i < n) g_rs[i] = sm[threadIdx.x] - v;   // exclusive within block
    if (threadIdx.x == 1023) g_bsum[blockIdx.x] = sm[1023];
}

// add prior block sums (tree-reduced) + finalize rowstarts + dis
__global__ void k_scan3(int n, int e) {
    __shared__ int red[128];
    int b = blockIdx.x;
    int t = threadIdx.x;
    if (t < 128) red[t] = (t < b) ? g_bsum[t] : 0;
    __syncthreads();
    for (int off = 64; off > 0; off >>= 1) {
        if (t < (unsigned)off) red[t] += red[t + off];
        __syncthreads();
    }
    int pre = red[0];
    int i = b * 1024 + t;
    if (i < n) {
        int v = g_rs[i] + pre;
        g_rs[i] = v;
        g_cur[i] = v;
        g_dis[i] = rsqrtf((float)(g_cnt[i] + 1));   // +1 self loop
    }
    if (i == 0) g_rs[n] = e;
}

__global__ void k_scatter(const int* __restrict__ src, const int* __restrict__ dst, int e) {
    int i = blockIdx.x * blockDim.x + threadIdx.x;
    if (i < e) {
        int s = src[i], d = dst[i];
        int p = atomicAdd(&g_cur[d], 1);
        g_csrs[p] = s;
        g_csrw[p] = g_dis[s] * g_dis[d];
    }
}

// ---------------- MMA helpers ----------------
__device__ __forceinline__ void mma_f16(float* c, const unsigned* a, unsigned b0, unsigned b1) {
    asm volatile(
        "mma.sync.aligned.m16n8k16.row.col.f32.f16.f16.f32 "
        "{%0,%1,%2,%3}, {%4,%5,%6,%7}, {%8,%9}, {%0,%1,%2,%3};\n"
        : "+f"(c[0]), "+f"(c[1]), "+f"(c[2]), "+f"(c[3])
        : "r"(a[0]), "r"(a[1]), "r"(a[2]), "r"(a[3]), "r"(b0), "r"(b1));
}

__device__ __forceinline__ void split_pack_h(float x, float y, unsigned& hi, unsigned& lo) {
    __half2 h = __floats2half2_rn(x, y);
    float2 hf = __half22float2(h);
    __half2 l = __floats2half2_rn(x - hf.x, y - hf.y);
    hi = *(unsigned*)&h;
    lo = *(unsigned*)&l;
}

#define BSTR 136   // smem stride in uint32 -> conflict-free frag loads

// ---------------- GEMM layer 0: X fp32, 2-pass split ----------------
__global__ void __launch_bounds__(256)
k_gemm(const float* __restrict__ X, const float* __restrict__ W,
       __half* __restrict__ H, int n) {
    __shared__ unsigned Bh[64 * BSTR];

    int tid = threadIdx.x;
    for (int i = tid; i < 64 * 128; i += 256) {
        int j = i >> 7, c = i & 127;
        float w0 = W[(2 * j) * 128 + c];
        float w1 = W[(2 * j + 1) * 128 + c];
        __half2 h = __floats2half2_rn(w0, w1);
        Bh[j * BSTR + c] = *(unsigned*)&h;
    }
    __syncthreads();

    int wid = tid >> 5, lane = tid & 31;
    int warp_m = wid >> 1, warp_n = wid & 1;
    int g = lane >> 2, tg = lane & 3;
    int rbase = blockIdx.x * 128 + warp_m * 32;
    int cbase = warp_n * 64;
    int nclamp = n - 1;

    float acc[2][8][4];
#pragma unroll
    for (int mf = 0; mf < 2; mf++)
#pragma unroll
        for (int nt = 0; nt < 8; nt++)
#pragma unroll
            for (int q = 0; q < 4; q++) acc[mf][nt][q] = 0.0f;

    for (int k0 = 0; k0 < 128; k0 += 16) {
        unsigned ah[2][4], al[2][4];
#pragma unroll
        for (int mf = 0; mf < 2; mf++) {
            int r0 = rbase + mf * 16 + g;
            int r1 = r0 + 8;
            if (r0 > nclamp) r0 = nclamp;
            if (r1 > nclamp) r1 = nclamp;
            const float* p0 = X + (size_t)r0 * D + k0 + 2 * tg;
            const float* p1 = X + (size_t)r1 * D + k0 + 2 * tg;
            float2 f00 = *(const float2*)(p0);
            float2 f01 = *(const float2*)(p0 + 8);
            float2 f10 = *(const float2*)(p1);
            float2 f11 = *(const float2*)(p1 + 8);
            split_pack_h(f00.x, f00.y, ah[mf][0], al[mf][0]);
            split_pack_h(f10.x, f10.y, ah[mf][1], al[mf][1]);
            split_pack_h(f01.x, f01.y, ah[mf][2], al[mf][2]);
            split_pack_h(f11.x, f11.y, ah[mf][3], al[mf][3]);
        }
#pragma unroll
        for (int nt = 0; nt < 8; nt++) {
            int c = cbase + nt * 8 + g;
            int i0 = (k0 / 2 + tg) * BSTR + c;
            int i1 = i0 + 4 * BSTR;
            unsigned b0 = Bh[i0], b1 = Bh[i1];
#pragma unroll
            for (int mf = 0; mf < 2; mf++) {
                mma_f16(acc[mf][nt], al[mf], b0, b1);
                mma_f16(acc[mf][nt], ah[mf], b0, b1);
            }
        }
    }

#pragma unroll
    for (int mf = 0; mf < 2; mf++) {
        int r0 = rbase + mf * 16 + g;
        int r1 = r0 + 8;
#pragma unroll
        for (int nt = 0; nt < 8; nt++) {
            int c = cbase + nt * 8 + 2 * tg;
            if (r0 < n) {
                __half2 v = __floats2half2_rn(acc[mf][nt][0], acc[mf][nt][1]);
                *(__half2*)(H + (size_t)r0 * D + c) = v;
            }
            if (r1 < n) {
                __half2 v = __floats2half2_rn(acc[mf][nt][2], acc[mf][nt][3]);
                *(__half2*)(H + (size_t)r1 * D + c) = v;
            }
        }
    }
}

// ---------------- GEMM layers 1-2: X fp16, single pass ----------------
__global__ void __launch_bounds__(256)
k_gemm_h(const __half* __restrict__ X, const float* __restrict__ W,
         __half* __restrict__ H, int n) {
    __shared__ unsigned Bh[64 * BSTR];

    int tid = threadIdx.x;
    for (int i = tid; i < 64 * 128; i += 256) {
        int j = i >> 7, c = i & 127;
        float w0 = W[(2 * j) * 128 + c];
        float w1 = W[(2 * j + 1) * 128 + c];
        __half2 h = __floats2half2_rn(w0, w1);
        Bh[j * BSTR + c] = *(unsigned*)&h;
    }
    __syncthreads();

    int wid = tid >> 5, lane = tid & 31;
    int warp_m = wid >> 1, warp_n = wid & 1;
    int g = lane >> 2, tg = lane & 3;
    int rbase = blockIdx.x * 128 + warp_m * 32;
    int cbase = warp_n * 64;
    int nclamp = n - 1;

    float acc[2][8][4];
#pragma unroll
    for (int mf = 0; mf < 2; mf++)
#pragma unroll
        for (int nt = 0; nt < 8; nt++)
#pragma unroll
            for (int q = 0; q < 4; q++) acc[mf][nt][q] = 0.0f;

    for (int k0 = 0; k0 < 128; k0 += 16) {
        unsigned a[2][4];
#pragma unroll
        for (int mf = 0; mf < 2; mf++) {
            int r0 = rbase + mf * 16 + g;
            int r1 = r0 + 8;
            if (r0 > nclamp) r0 = nclamp;
            if (r1 > nclamp) r1 = nclamp;
            const __half* p0 = X + (size_t)r0 * D + k0 + 2 * tg;
            const __half* p1 = X + (size_t)r1 * D + k0 + 2 * tg;
            a[mf][0] = *(const unsigned*)(p0);
            a[mf][1] = *(const unsigned*)(p1);
            a[mf][2] = *(const unsigned*)(p0 + 8);
            a[mf][3] = *(const unsigned*)(p1 + 8);
        }
#pragma unroll
        for (int nt = 0; nt < 8; nt++) {
            int c = cbase + nt * 8 + g;
            int i0 = (k0 / 2 + tg) * BSTR + c;
            int i1 = i0 + 4 * BSTR;
            unsigned b0 = Bh[i0], b1 = Bh[i1];
#pragma unroll
            for (int mf = 0; mf < 2; mf++)
                mma_f16(acc[mf][nt], a[mf], b0, b1);
        }
    }

#pragma unroll
    for (int mf = 0; mf < 2; mf++) {
        int r0 = rbase + mf * 16 + g;
        int r1 = r0 + 8;
#pragma unroll
        for (int nt = 0; nt < 8; nt++) {
            int c = cbase + nt * 8 + 2 * tg;
            if (r0 < n) {
                __half2 v = __floats2half2_rn(acc[mf][nt][0], acc[mf][nt][1]);
                *(__half2*)(H + (size_t)r0 * D + c) = v;
            }
            if (r1 < n) {
                __half2 v = __floats2half2_rn(acc[mf][nt][2], acc[mf][nt][3]);
                *(__half2*)(H + (size_t)r1 * D + c) = v;
            }
        }
    }
}

// ---------------- aggregation (templated output: fp16 inter-layer, fp32 final) ----------------
template <bool HALF_OUT>
__global__ void k_agg(const __half* __restrict__ Hh, const float* __restrict__ bias,
                      void* __restrict__ outv, int n) {
    int warp = (blockIdx.x * blockDim.x + threadIdx.x) >> 5;
    int lane = threadIdx.x & 31;
    if (warp >= n) return;
    const uint2* H2 = (const uint2*)Hh;

    float dv = g_dis[warp];
    float sw = dv * dv;

    uint2 uv = H2[(size_t)warp * 32 + lane];
    float2 v0 = __half22float2(*(__half2*)&uv.x);
    float2 v1 = __half22float2(*(__half2*)&uv.y);
    float ax = sw * v0.x, ay = sw * v0.y, az = sw * v1.x, aw = sw * v1.y;

    int e = g_rs[warp], end = g_rs[warp + 1];
    for (; e + 8 <= end; e += 8) {
        int   s[8];
        float w[8];
        uint2 u[8];
#pragma unroll
        for (int j = 0; j < 8; j++) { s[j] = g_csrs[e + j]; w[j] = g_csrw[e + j]; }
#pragma unroll
        for (int j = 0; j < 8; j++) u[j] = H2[(size_t)s[j] * 32 + lane];
#pragma unroll
        for (int j = 0; j < 8; j++) {
            float2 a = __half22float2(*(__half2*)&u[j].x);
            float2 b = __half22float2(*(__half2*)&u[j].y);
            ax = fmaf(w[j], a.x, ax); ay = fmaf(w[j], a.y, ay);
            az = fmaf(w[j], b.x, az); aw = fmaf(w[j], b.y, aw);
        }
    }
    for (; e + 4 <= end; e += 4) {
        int   s[4];
        float w[4];
        uint2 u[4];
#pragma unroll
        for (int j = 0; j < 4; j++) { s[j] = g_csrs[e + j]; w[j] = g_csrw[e + j]; }
#pragma unroll
        for (int j = 0; j < 4; j++) u[j] = H2[(size_t)s[j] * 32 + lane];
#pragma unroll
        for (int j = 0; j < 4; j++) {
            float2 a = __half22float2(*(__half2*)&u[j].x);
            float2 b = __half22float2(*(__half2*)&u[j].y);
            ax = fmaf(w[j], a.x, ax); ay = fmaf(w[j], a.y, ay);
            az = fmaf(w[j], b.x, az); aw = fmaf(w[j], b.y, aw);
        }
    }
    for (; e < end; e++) {
        int s0 = g_csrs[e];
        float w0 = g_csrw[e];
        uint2 u = H2[(size_t)s0 * 32 + lane];
        float2 a = __half22float2(*(__half2*)&u.x), b = __half22float2(*(__half2*)&u.y);
        ax = fmaf(w0, a.x, ax); ay = fmaf(w0, a.y, ay); az = fmaf(w0, b.x, az); aw = fmaf(w0, b.y, aw);
    }

    float4 b4 = ((const float4*)bias)[lane];
    ax += b4.x; ay += b4.y; az += b4.z; aw += b4.w;

    if (HALF_OUT) {
        __half2 h0 = __floats2half2_rn(ax, ay);
        __half2 h1 = __floats2half2_rn(az, aw);
        uint2 o;
        o.x = *(unsigned*)&h0;
        o.y = *(unsigned*)&h1;
        ((uint2*)outv)[(size_t)warp * 32 + lane] = o;
    } else {
        float4 o = make_float4(ax, ay, az, aw);
        ((float4*)outv)[(size_t)warp * 32 + lane] = o;
    }
}

// ---------------- launch (single stream, graph-capture safe) ----------------
extern "C" void kernel_launch(void* const* d_in, const int* in_sizes, int n_in,
                              void* d_out, int out_size) {
    const float* feat = (const float*)d_in[0];
    const int*   ei   = (const int*)d_in[1];
    const float* W0 = (const float*)d_in[2];
    const float* b0 = (const float*)d_in[3];
    const float* W1 = (const float*)d_in[4];
    const float* b1 = (const float*)d_in[5];
    const float* W2 = (const float*)d_in[6];
    const float* b2 = (const float*)d_in[7];

    int n = in_sizes[0] / D;
    int e = in_sizes[1] / 2;
    if (n > NMAX) n = NMAX;
    if (e > EMAX) e = EMAX;
    const int* src = ei;
    const int* dstp = ei + e;

    __half *Hp, *Ap;
    cudaGetSymbolAddress((void**)&Hp, g_H);
    cudaGetSymbolAddress((void**)&Ap, g_A);

    int nb = (n + 1023) / 1024;
    int gm = (n + 127) / 128;
    int ga = (int)(((long long)n * 32 + 255) / 256);

    // preprocessing: degree -> scan -> CSR
    k_zero<<<(n + 255) / 256, 256>>>(n);
    k_count<<<(e + 255) / 256, 256>>>(dstp, e);
    k_scan1<<<nb, 1024>>>(n);
    k_scan3<<<nb, 1024>>>(n, e);
    k_scatter<<<(e + 255) / 256, 256>>>(src, dstp, e);

    // layer 0: fp32 features, 2-pass split
    k_gemm<<<gm, 256>>>(feat, W0, Hp, n);
    k_agg<true><<<ga, 256>>>(Hp, b0, Ap, n);
    // layer 1: fp16 input, single pass
    k_gemm_h<<<gm, 256>>>(Ap, W1, Hp, n);
    k_agg<true><<<ga, 256>>>(Hp, b1, Ap, n);
    // layer 2
    k_gemm_h<<<gm, 256>>>(Ap, W2, Hp, n);
    k_agg<false><<<ga, 256>>>(Hp, b2, d_out, n);
}

// round 7
// speedup vs baseline: 2.0045x; 1.1038x over previous
#include <cuda_runtime.h>
#include <cuda_fp16.h>
#include <cstdint>
#include <cstddef>

#define NMAX 100000
#define EMAX 1600000
#define D 128

// ---------------- static device scratch ----------------
__device__ __half g_H[(size_t)NMAX * D];    // ping buffer, fp16
__device__ __half g_A[(size_t)NMAX * D];    // pong buffer, fp16
__device__ int    g_cnt[NMAX];
__device__ float  g_dis[NMAX];
__device__ int    g_rs[NMAX + 1];
__device__ int    g_cur[NMAX];
__device__ int    g_bsum[256];
__device__ int    g_csrs[EMAX];
__device__ float  g_csrw[EMAX];
__device__ float  g_Wt[128 * 128];          // W0*W1
__device__ float  g_W012[128 * 128];        // W0*W1*W2
__device__ float  g_c1[128];                // b0*W1*W2
__device__ float  g_c2[128];                // b1*W2
__device__ float  g_u1[NMAX];               // A*1
__device__ float  g_u2[NMAX];               // A^2*1

// ---------------- graph preprocessing ----------------
__global__ void k_zero(int n) {
    int i = blockIdx.x * blockDim.x + threadIdx.x;
    if (i < n) g_cnt[i] = 0;
}

__global__ void k_count(const int* __restrict__ dst, int e) {
    int i = blockIdx.x * blockDim.x + threadIdx.x;
    if (i < e) atomicAdd(&g_cnt[dst[i]], 1);
}

__global__ void k_scan1(int n) {
    __shared__ int sm[1024];
    int i = blockIdx.x * 1024 + threadIdx.x;
    int v = (i < n) ? g_cnt[i] : 0;
    sm[threadIdx.x] = v;
    __syncthreads();
    for (int off = 1; off < 1024; off <<= 1) {
        int t = (threadIdx.x >= (unsigned)off) ? sm[threadIdx.x - off] : 0;
        __syncthreads();
        sm[threadIdx.x] += t;
        __syncthreads();
    }
    if (i < n) g_rs[i] = sm[threadIdx.x] - v;   // exclusive within block
    if (threadIdx.x == 1023) g_bsum[blockIdx.x] = sm[1023];
}

__global__ void k_scan3(int n, int e) {
    __shared__ int red[128];
    int b = blockIdx.x;
    int t = threadIdx.x;
    if (t < 128) red[t] = (t < b) ? g_bsum[t] : 0;
    __syncthreads();
    for (int off = 64; off > 0; off >>= 1) {
        if (t < (unsigned)off) red[t] += red[t + off];
        __syncthreads();
    }
    int pre = red[0];
    int i = b * 1024 + t;
    if (i < n) {
        int v = g_rs[i] + pre;
        g_rs[i] = v;
        g_cur[i] = v;
        g_dis[i] = rsqrtf((float)(g_cnt[i] + 1));   // +1 self loop
    }
    if (i == 0) g_rs[n] = e;
}

__global__ void k_scatter(const int* __restrict__ src, const int* __restrict__ dst, int e) {
    int i = blockIdx.x * blockDim.x + threadIdx.x;
    if (i < e) {
        int s = src[i], d = dst[i];
        int p = atomicAdd(&g_cur[d], 1);
        g_csrs[p] = s;
        g_csrw[p] = g_dis[s] * g_dis[d];
    }
}

// ---------------- tiny fp32 matmul: C[128x128] = A*B ----------------
__global__ void k_mm128(const float* __restrict__ A, const float* __restrict__ B,
                        float* __restrict__ C) {
    int id = blockIdx.x * 256 + threadIdx.x;
    int r = id >> 7, c = id & 127;
    float s = 0.0f;
#pragma unroll 8
    for (int k = 0; k < 128; k++) s = fmaf(A[r * 128 + k], B[k * 128 + c], s);
    C[id] = s;
}

// ---------------- bias correction vectors: c1 = b0*W1*W2, c2 = b1*W2 ----------------
__global__ void k_cvec(const float* __restrict__ b0, const float* __restrict__ b1,
                       const float* __restrict__ W1, const float* __restrict__ W2) {
    __shared__ float t1[128];
    int j = threadIdx.x;
    float s = 0.0f;
    for (int k = 0; k < 128; k++) s = fmaf(b0[k], W1[k * 128 + j], s);
    t1[j] = s;
    __syncthreads();
    float s1 = 0.0f, s2 = 0.0f;
    for (int k = 0; k < 128; k++) {
        float w = W2[k * 128 + j];
        s1 = fmaf(t1[k], w, s1);
        s2 = fmaf(b1[k], w, s2);
    }
    g_c1[j] = s1;
    g_c2[j] = s2;
}

// ---------------- scalar aggregations: u1 = A*1, u2 = A*u1 ----------------
__global__ void k_aggs1(int n) {
    int v = blockIdx.x * blockDim.x + threadIdx.x;
    if (v >= n) return;
    float dv = g_dis[v];
    float s = dv * dv;
    int end = g_rs[v + 1];
    for (int e = g_rs[v]; e < end; e++) s += g_csrw[e];
    g_u1[v] = s;
}

__global__ void k_aggs2(int n) {
    int v = blockIdx.x * blockDim.x + threadIdx.x;
    if (v >= n) return;
    float dv = g_dis[v];
    float s = dv * dv * g_u1[v];
    int end = g_rs[v + 1];
    for (int e = g_rs[v]; e < end; e++) s += g_csrw[e] * g_u1[g_csrs[e]];
    g_u2[v] = s;
}

// ---------------- MMA helpers ----------------
__device__ __forceinline__ void mma_f16(float* c, const unsigned* a, unsigned b0, unsigned b1) {
    asm volatile(
        "mma.sync.aligned.m16n8k16.row.col.f32.f16.f16.f32 "
        "{%0,%1,%2,%3}, {%4,%5,%6,%7}, {%8,%9}, {%0,%1,%2,%3};\n"
        : "+f"(c[0]), "+f"(c[1]), "+f"(c[2]), "+f"(c[3])
        : "r"(a[0]), "r"(a[1]), "r"(a[2]), "r"(a[3]), "r"(b0), "r"(b1));
}

__device__ __forceinline__ void split_pack_h(float x, float y, unsigned& hi, unsigned& lo) {
    __half2 h = __floats2half2_rn(x, y);
    float2 hf = __half22float2(h);
    __half2 l = __floats2half2_rn(x - hf.x, y - hf.y);
    hi = *(unsigned*)&h;
    lo = *(unsigned*)&l;
}

#define BSTR 136   // smem stride in uint32 -> conflict-free frag loads

// ---------------- GEMM: Y = X(fp32) @ W012, 2-pass split ----------------
__global__ void __launch_bounds__(256)
k_gemm(const float* __restrict__ X, const float* __restrict__ W,
       __half* __restrict__ H, int n) {
    __shared__ unsigned Bh[64 * BSTR];

    int tid = threadIdx.x;
    for (int i = tid; i < 64 * 128; i += 256) {
        int j = i >> 7, c = i & 127;
        float w0 = W[(2 * j) * 128 + c];
        float w1 = W[(2 * j + 1) * 128 + c];
        __half2 h = __floats2half2_rn(w0, w1);
        Bh[j * BSTR + c] = *(unsigned*)&h;
    }
    __syncthreads();

    int wid = tid >> 5, lane = tid & 31;
    int warp_m = wid >> 1, warp_n = wid & 1;
    int g = lane >> 2, tg = lane & 3;
    int rbase = blockIdx.x * 128 + warp_m * 32;
    int cbase = warp_n * 64;
    int nclamp = n - 1;

    float acc[2][8][4];
#pragma unroll
    for (int mf = 0; mf < 2; mf++)
#pragma unroll
        for (int nt = 0; nt < 8; nt++)
#pragma unroll
            for (int q = 0; q < 4; q++) acc[mf][nt][q] = 0.0f;

    for (int k0 = 0; k0 < 128; k0 += 16) {
        unsigned ah[2][4], al[2][4];
#pragma unroll
        for (int mf = 0; mf < 2; mf++) {
            int r0 = rbase + mf * 16 + g;
            int r1 = r0 + 8;
            if (r0 > nclamp) r0 = nclamp;
            if (r1 > nclamp) r1 = nclamp;
            const float* p0 = X + (size_t)r0 * D + k0 + 2 * tg;
            const float* p1 = X + (size_t)r1 * D + k0 + 2 * tg;
            float2 f00 = *(const float2*)(p0);
            float2 f01 = *(const float2*)(p0 + 8);
            float2 f10 = *(const float2*)(p1);
            float2 f11 = *(const float2*)(p1 + 8);
            split_pack_h(f00.x, f00.y, ah[mf][0], al[mf][0]);
            split_pack_h(f10.x, f10.y, ah[mf][1], al[mf][1]);
            split_pack_h(f01.x, f01.y, ah[mf][2], al[mf][2]);
            split_pack_h(f11.x, f11.y, ah[mf][3], al[mf][3]);
        }
#pragma unroll
        for (int nt = 0; nt < 8; nt++) {
            int c = cbase + nt * 8 + g;
            int i0 = (k0 / 2 + tg) * BSTR + c;
            int i1 = i0 + 4 * BSTR;
            unsigned b0 = Bh[i0], b1 = Bh[i1];
#pragma unroll
            for (int mf = 0; mf < 2; mf++) {
                mma_f16(acc[mf][nt], al[mf], b0, b1);
                mma_f16(acc[mf][nt], ah[mf], b0, b1);
            }
        }
    }

#pragma unroll
    for (int mf = 0; mf < 2; mf++) {
        int r0 = rbase + mf * 16 + g;
        int r1 = r0 + 8;
#pragma unroll
        for (int nt = 0; nt < 8; nt++) {
            int c = cbase + nt * 8 + 2 * tg;
            if (r0 < n) {
                __half2 v = __floats2half2_rn(acc[mf][nt][0], acc[mf][nt][1]);
                *(__half2*)(H + (size_t)r0 * D + c) = v;
            }
            if (r1 < n) {
                __half2 v = __floats2half2_rn(acc[mf][nt][2], acc[mf][nt][3]);
                *(__half2*)(H + (size_t)r1 * D + c) = v;
            }
        }
    }
}

// ---------------- feature aggregation core (warp per node) ----------------
__device__ __forceinline__ void agg_core(const uint2* __restrict__ H2, int warp, int lane,
                                         float& ax, float& ay, float& az, float& aw) {
    float dv = g_dis[warp];
    float sw = dv * dv;

    uint2 uv = H2[(size_t)warp * 32 + lane];
    float2 v0 = __half22float2(*(__half2*)&uv.x);
    float2 v1 = __half22float2(*(__half2*)&uv.y);
    ax = sw * v0.x; ay = sw * v0.y; az = sw * v1.x; aw = sw * v1.y;

    int e = g_rs[warp], end = g_rs[warp + 1];
    for (; e + 8 <= end; e += 8) {
        int   s[8];
        float w[8];
        uint2 u[8];
#pragma unroll
        for (int j = 0; j < 8; j++) { s[j] = g_csrs[e + j]; w[j] = g_csrw[e + j]; }
#pragma unroll
        for (int j = 0; j < 8; j++) u[j] = H2[(size_t)s[j] * 32 + lane];
#pragma unroll
        for (int j = 0; j < 8; j++) {
            float2 a = __half22float2(*(__half2*)&u[j].x);
            float2 b = __half22float2(*(__half2*)&u[j].y);
            ax = fmaf(w[j], a.x, ax); ay = fmaf(w[j], a.y, ay);
            az = fmaf(w[j], b.x, az); aw = fmaf(w[j], b.y, aw);
        }
    }
    for (; e + 4 <= end; e += 4) {
        int   s[4];
        float w[4];
        uint2 u[4];
#pragma unroll
        for (int j = 0; j < 4; j++) { s[j] = g_csrs[e + j]; w[j] = g_csrw[e + j]; }
#pragma unroll
        for (int j = 0; j < 4; j++) u[j] = H2[(size_t)s[j] * 32 + lane];
#pragma unroll
        for (int j = 0; j < 4; j++) {
            float2 a = __half22float2(*(__half2*)&u[j].x);
            float2 b = __half22float2(*(__half2*)&u[j].y);
            ax = fmaf(w[j], a.x, ax); ay = fmaf(w[j], a.y, ay);
            az = fmaf(w[j], b.x, az); aw = fmaf(w[j], b.y, aw);
        }
    }
    for (; e < end; e++) {
        int s0 = g_csrs[e];
        float w0 = g_csrw[e];
        uint2 u = H2[(size_t)s0 * 32 + lane];
        float2 a = __half22float2(*(__half2*)&u.x), b = __half22float2(*(__half2*)&u.y);
        ax = fmaf(w0, a.x, ax); ay = fmaf(w0, a.y, ay); az = fmaf(w0, b.x, az); aw = fmaf(w0, b.y, aw);
    }
}

// mid aggregation: pure A-apply, fp16 -> fp16, no bias
__global__ void k_agg_mid(const __half* __restrict__ Hh, __half* __restrict__ Oh, int n) {
    int warp = (blockIdx.x * blockDim.x + threadIdx.x) >> 5;
    int lane = threadIdx.x & 31;
    if (warp >= n) return;
    float ax, ay, az, aw;
    agg_core((const uint2*)Hh, warp, lane, ax, ay, az, aw);
    __half2 h0 = __floats2half2_rn(ax, ay);
    __half2 h1 = __floats2half2_rn(az, aw);
    uint2 o;
    o.x = *(unsigned*)&h0;
    o.y = *(unsigned*)&h1;
    ((uint2*)Oh)[(size_t)warp * 32 + lane] = o;
}

// final aggregation: A-apply + rank-1 bias corrections + b2, fp32 out
__global__ void k_agg_fin(const __half* __restrict__ Hh, const float* __restrict__ b2,
                          float* __restrict__ out, int n) {
    int warp = (blockIdx.x * blockDim.x + threadIdx.x) >> 5;
    int lane = threadIdx.x & 31;
    if (warp >= n) return;
    float ax, ay, az, aw;
    agg_core((const uint2*)Hh, warp, lane, ax, ay, az, aw);

    float u2v = g_u2[warp];
    float u1v = g_u1[warp];
    float4 c1 = ((const float4*)g_c1)[lane];
    float4 c2 = ((const float4*)g_c2)[lane];
    float4 bb = ((const float4*)b2)[lane];

    float4 o;
    o.x = ax + u2v * c1.x + u1v * c2.x + bb.x;
    o.y = ay + u2v * c1.y + u1v * c2.y + bb.y;
    o.z = az + u2v * c1.z + u1v * c2.z + bb.z;
    o.w = aw + u2v * c1.w + u1v * c2.w + bb.w;
    ((float4*)out)[(size_t)warp * 32 + lane] = o;
}

// ---------------- launch (single stream, graph-capture safe) ----------------
extern "C" void kernel_launch(void* const* d_in, const int* in_sizes, int n_in,
                              void* d_out, int out_size) {
    const float* feat = (const float*)d_in[0];
    const int*   ei   = (const int*)d_in[1];
    const float* W0 = (const float*)d_in[2];
    const float* b0 = (const float*)d_in[3];
    const float* W1 = (const float*)d_in[4];
    const float* b1 = (const float*)d_in[5];
    const float* W2 = (const float*)d_in[6];
    const float* b2 = (const float*)d_in[7];

    int n = in_sizes[0] / D;
    int e = in_sizes[1] / 2;
    if (n > NMAX) n = NMAX;
    if (e > EMAX) e = EMAX;
    const int* src = ei;
    const int* dstp = ei + e;

    __half *Hp, *Ap;
    float *Wtp, *W012p;
    cudaGetSymbolAddress((void**)&Hp, g_H);
    cudaGetSymbolAddress((void**)&Ap, g_A);
    cudaGetSymbolAddress((void**)&Wtp, g_Wt);
    cudaGetSymbolAddress((void**)&W012p, g_W012);

    int nb = (n + 1023) / 1024;
    int gm = (n + 127) / 128;
    int ga = (int)(((long long)n * 32 + 255) / 256);
    int gn = (n + 255) / 256;

    // preprocessing: degree -> scan -> CSR
    k_zero<<<gn, 256>>>(n);
    k_count<<<(e + 255) / 256, 256>>>(dstp, e);
    k_scan1<<<nb, 1024>>>(n);
    k_scan3<<<nb, 1024>>>(n, e);
    k_scatter<<<(e + 255) / 256, 256>>>(src, dstp, e);

    // collapsed weights + bias-correction vectors
    k_mm128<<<64, 256>>>(W0, W1, Wtp);
    k_mm128<<<64, 256>>>(Wtp, W2, W012p);
    k_cvec<<<1, 128>>>(b0, b1, W1, W2);

    // one GEMM: Y = X * W012
    k_gemm<<<gm, 256>>>(feat, W012p, Hp, n);

    // scalar aggregations for bias corrections
    k_aggs1<<<gn, 256>>>(n);
    k_aggs2<<<gn, 256>>>(n);

    // A^3 applied to Y
    k_agg_mid<<<ga, 256>>>(Hp, Ap, n);
    k_agg_mid<<<ga, 256>>>(Ap, Hp, n);
    k_agg_fin<<<ga, 256>>>(Hp, b2, (float*)d_out, n);
}

// round 8
// speedup vs baseline: 2.2070x; 1.1010x over previous
#include <cuda_runtime.h>
#include <cuda_fp16.h>
#include <cstdint>
#include <cstddef>

#define NMAX 100000
#define EMAX 1600000
#define D 128

// ---------------- static device scratch ----------------
__device__ __half g_H[(size_t)NMAX * D];    // ping buffer, fp16
__device__ __half g_A[(size_t)NMAX * D];    // pong buffer, fp16
__device__ int    g_cnt[NMAX];
__device__ float  g_dis[NMAX];
__device__ int    g_rs[NMAX + 1];
__device__ int    g_cur[NMAX];
__device__ int    g_bsum[256];
__device__ int    g_csrs[EMAX];
__device__ float  g_csrw[EMAX];
__device__ float  g_Wt[128 * 128];          // W0*W1
__device__ float  g_W012[128 * 128];        // W0*W1*W2
__device__ float  g_c1[128];                // b0*W1*W2
__device__ float  g_c2[128];                // b1*W2
__device__ float  g_u1[NMAX];               // A*1
__device__ float  g_u2[NMAX];               // A^2*1

// ---------------- graph preprocessing ----------------
__global__ void k_zero(int n) {
    int i = blockIdx.x * blockDim.x + threadIdx.x;
    if (i < n) g_cnt[i] = 0;
}

__global__ void k_count(const int* __restrict__ dst, int e) {
    int i = blockIdx.x * blockDim.x + threadIdx.x;
    if (i < e) atomicAdd(&g_cnt[dst[i]], 1);
}

__global__ void k_scan1(int n) {
    __shared__ int sm[1024];
    int i = blockIdx.x * 1024 + threadIdx.x;
    int v = (i < n) ? g_cnt[i] : 0;
    sm[threadIdx.x] = v;
    __syncthreads();
    for (int off = 1; off < 1024; off <<= 1) {
        int t = (threadIdx.x >= (unsigned)off) ? sm[threadIdx.x - off] : 0;
        __syncthreads();
        sm[threadIdx.x] += t;
        __syncthreads();
    }
    if (i < n) g_rs[i] = sm[threadIdx.x] - v;   // exclusive within block
    if (threadIdx.x == 1023) g_bsum[blockIdx.x] = sm[1023];
}

__global__ void k_scan3(int n, int e) {
    __shared__ int red[128];
    int b = blockIdx.x;
    int t = threadIdx.x;
    if (t < 128) red[t] = (t < b) ? g_bsum[t] : 0;
    __syncthreads();
    for (int off = 64; off > 0; off >>= 1) {
        if (t < (unsigned)off) red[t] += red[t + off];
        __syncthreads();
    }
    int pre = red[0];
    int i = b * 1024 + t;
    if (i < n) {
        int v = g_rs[i] + pre;
        g_rs[i] = v;
        g_cur[i] = v;
        g_dis[i] = rsqrtf((float)(g_cnt[i] + 1));   // +1 self loop
    }
    if (i == 0) g_rs[n] = e;
}

__global__ void k_scatter(const int* __restrict__ src, const int* __restrict__ dst, int e) {
    int i = blockIdx.x * blockDim.x + threadIdx.x;
    if (i < e) {
        int s = src[i], d = dst[i];
        int p = atomicAdd(&g_cur[d], 1);
        g_csrs[p] = s;
        g_csrw[p] = g_dis[s] * g_dis[d];
    }
}

// ---------------- tiny fp32 matmul: C[128x128] = A*B ----------------
__global__ void k_mm128(const float* __restrict__ A, const float* __restrict__ B,
                        float* __restrict__ C) {
    int id = blockIdx.x * 256 + threadIdx.x;
    int r = id >> 7, c = id & 127;
    float s = 0.0f;
#pragma unroll 8
    for (int k = 0; k < 128; k++) s = fmaf(A[r * 128 + k], B[k * 128 + c], s);
    C[id] = s;
}

// ---------------- bias correction vectors: c1 = b0*W1*W2, c2 = b1*W2 ----------------
__global__ void k_cvec(const float* __restrict__ b0, const float* __restrict__ b1,
                       const float* __restrict__ W1, const float* __restrict__ W2) {
    __shared__ float t1[128];
    int j = threadIdx.x;
    float s = 0.0f;
    for (int k = 0; k < 128; k++) s = fmaf(b0[k], W1[k * 128 + j], s);
    t1[j] = s;
    __syncthreads();
    float s1 = 0.0f, s2 = 0.0f;
    for (int k = 0; k < 128; k++) {
        float w = W2[k * 128 + j];
        s1 = fmaf(t1[k], w, s1);
        s2 = fmaf(b1[k], w, s2);
    }
    g_c1[j] = s1;
    g_c2[j] = s2;
}

// ---------------- scalar aggregations: u1 = A*1, u2 = A*u1 ----------------
__global__ void k_aggs1(int n) {
    int v = blockIdx.x * blockDim.x + threadIdx.x;
    if (v >= n) return;
    float dv = g_dis[v];
    float s = dv * dv;
    int end = g_rs[v + 1];
    for (int e = g_rs[v]; e < end; e++) s += g_csrw[e];
    g_u1[v] = s;
}

__global__ void k_aggs2(int n) {
    int v = blockIdx.x * blockDim.x + threadIdx.x;
    if (v >= n) return;
    float dv = g_dis[v];
    float s = dv * dv * g_u1[v];
    int end = g_rs[v + 1];
    for (int e = g_rs[v]; e < end; e++) s += g_csrw[e] * g_u1[g_csrs[e]];
    g_u2[v] = s;
}

// ---------------- MMA helpers ----------------
__device__ __forceinline__ void mma_f16(float* c, const unsigned* a, unsigned b0, unsigned b1) {
    asm volatile(
        "mma.sync.aligned.m16n8k16.row.col.f32.f16.f16.f32 "
        "{%0,%1,%2,%3}, {%4,%5,%6,%7}, {%8,%9}, {%0,%1,%2,%3};\n"
        : "+f"(c[0]), "+f"(c[1]), "+f"(c[2]), "+f"(c[3])
        : "r"(a[0]), "r"(a[1]), "r"(a[2]), "r"(a[3]), "r"(b0), "r"(b1));
}

#define BSTR 136   // smem stride in uint32 -> conflict-free frag loads

// ---------------- GEMM: Y = X(fp32 -> fp16) @ W012, single pass ----------------
__global__ void __launch_bounds__(256)
k_gemm(const float* __restrict__ X, const float* __restrict__ W,
       __half* __restrict__ H, int n) {
    __shared__ unsigned Bh[64 * BSTR];

    int tid = threadIdx.x;
    for (int i = tid; i < 64 * 128; i += 256) {
        int j = i >> 7, c = i & 127;
        float w0 = W[(2 * j) * 128 + c];
        float w1 = W[(2 * j + 1) * 128 + c];
        __half2 h = __floats2half2_rn(w0, w1);
        Bh[j * BSTR + c] = *(unsigned*)&h;
    }
    __syncthreads();

    int wid = tid >> 5, lane = tid & 31;
    int warp_m = wid >> 1, warp_n = wid & 1;
    int g = lane >> 2, tg = lane & 3;
    int rbase = blockIdx.x * 128 + warp_m * 32;
    int cbase = warp_n * 64;
    int nclamp = n - 1;

    float acc[2][8][4];
#pragma unroll
    for (int mf = 0; mf < 2; mf++)
#pragma unroll
        for (int nt = 0; nt < 8; nt++)
#pragma unroll
            for (int q = 0; q < 4; q++) acc[mf][nt][q] = 0.0f;

    for (int k0 = 0; k0 < 128; k0 += 16) {
        unsigned a[2][4];
#pragma unroll
        for (int mf = 0; mf < 2; mf++) {
            int r0 = rbase + mf * 16 + g;
            int r1 = r0 + 8;
            if (r0 > nclamp) r0 = nclamp;
            if (r1 > nclamp) r1 = nclamp;
            const float* p0 = X + (size_t)r0 * D + k0 + 2 * tg;
            const float* p1 = X + (size_t)r1 * D + k0 + 2 * tg;
            float2 f00 = *(const float2*)(p0);
            float2 f01 = *(const float2*)(p0 + 8);
            float2 f10 = *(const float2*)(p1);
            float2 f11 = *(const float2*)(p1 + 8);
            __half2 h0 = __floats2half2_rn(f00.x, f00.y);
            __half2 h1 = __floats2half2_rn(f10.x, f10.y);
            __half2 h2 = __floats2half2_rn(f01.x, f01.y);
            __half2 h3 = __floats2half2_rn(f11.x, f11.y);
            a[mf][0] = *(unsigned*)&h0;
            a[mf][1] = *(unsigned*)&h1;
            a[mf][2] = *(unsigned*)&h2;
            a[mf][3] = *(unsigned*)&h3;
        }
#pragma unroll
        for (int nt = 0; nt < 8; nt++) {
            int c = cbase + nt * 8 + g;
            int i0 = (k0 / 2 + tg) * BSTR + c;
            int i1 = i0 + 4 * BSTR;
            unsigned b0 = Bh[i0], b1 = Bh[i1];
#pragma unroll
            for (int mf = 0; mf < 2; mf++)
                mma_f16(acc[mf][nt], a[mf], b0, b1);
        }
    }

#pragma unroll
    for (int mf = 0; mf < 2; mf++) {
        int r0 = rbase + mf * 16 + g;
        int r1 = r0 + 8;
#pragma unroll
        for (int nt = 0; nt < 8; nt++) {
            int c = cbase + nt * 8 + 2 * tg;
            if (r0 < n) {
                __half2 v = __floats2half2_rn(acc[mf][nt][0], acc[mf][nt][1]);
                *(__half2*)(H + (size_t)r0 * D + c) = v;
            }
            if (r1 < n) {
                __half2 v = __floats2half2_rn(acc[mf][nt][2], acc[mf][nt][3]);
                *(__half2*)(H + (size_t)r1 * D + c) = v;
            }
        }
    }
}

// ---------------- feature aggregation core (warp per node) ----------------
__device__ __forceinline__ void agg_core(const uint2* __restrict__ H2, int warp, int lane,
                                         float& ax, float& ay, float& az, float& aw) {
    float dv = g_dis[warp];
    float sw = dv * dv;

    uint2 uv = H2[(size_t)warp * 32 + lane];
    float2 v0 = __half22float2(*(__half2*)&uv.x);
    float2 v1 = __half22float2(*(__half2*)&uv.y);
    ax = sw * v0.x; ay = sw * v0.y; az = sw * v1.x; aw = sw * v1.y;

    int e = g_rs[warp], end = g_rs[warp + 1];
    for (; e + 8 <= end; e += 8) {
        int   s[8];
        float w[8];
        uint2 u[8];
#pragma unroll
        for (int j = 0; j < 8; j++) { s[j] = g_csrs[e + j]; w[j] = g_csrw[e + j]; }
#pragma unroll
        for (int j = 0; j < 8; j++) u[j] = H2[(size_t)s[j] * 32 + lane];
#pragma unroll
        for (int j = 0; j < 8; j++) {
            float2 a = __half22float2(*(__half2*)&u[j].x);
            float2 b = __half22float2(*(__half2*)&u[j].y);
            ax = fmaf(w[j], a.x, ax); ay = fmaf(w[j], a.y, ay);
            az = fmaf(w[j], b.x, az); aw = fmaf(w[j], b.y, aw);
        }
    }
    for (; e + 4 <= end; e += 4) {
        int   s[4];
        float w[4];
        uint2 u[4];
#pragma unroll
        for (int j = 0; j < 4; j++) { s[j] = g_csrs[e + j]; w[j] = g_csrw[e + j]; }
#pragma unroll
        for (int j = 0; j < 4; j++) u[j] = H2[(size_t)s[j] * 32 + lane];
#pragma unroll
        for (int j = 0; j < 4; j++) {
            float2 a = __half22float2(*(__half2*)&u[j].x);
            float2 b = __half22float2(*(__half2*)&u[j].y);
            ax = fmaf(w[j], a.x, ax); ay = fmaf(w[j], a.y, ay);
            az = fmaf(w[j], b.x, az); aw = fmaf(w[j], b.y, aw);
        }
    }
    for (; e < end; e++) {
        int s0 = g_csrs[e];
        float w0 = g_csrw[e];
        uint2 u = H2[(size_t)s0 * 32 + lane];
        float2 a = __half22float2(*(__half2*)&u.x), b = __half22float2(*(__half2*)&u.y);
        ax = fmaf(w0, a.x, ax); ay = fmaf(w0, a.y, ay); az = fmaf(w0, b.x, az); aw = fmaf(w0, b.y, aw);
    }
}

// mid aggregation: pure A-apply, fp16 -> fp16, no bias
__global__ void k_agg_mid(const __half* __restrict__ Hh, __half* __restrict__ Oh, int n) {
    int warp = (blockIdx.x * blockDim.x + threadIdx.x) >> 5;
    int lane = threadIdx.x & 31;
    if (warp >= n) return;
    float ax, ay, az, aw;
    agg_core((const uint2*)Hh, warp, lane, ax, ay, az, aw);
    __half2 h0 = __floats2half2_rn(ax, ay);
    __half2 h1 = __floats2half2_rn(az, aw);
    uint2 o;
    o.x = *(unsigned*)&h0;
    o.y = *(unsigned*)&h1;
    ((uint2*)Oh)[(size_t)warp * 32 + lane] = o;
}

// final aggregation: A-apply + rank-1 bias corrections + b2, fp32 out
__global__ void k_agg_fin(const __half* __restrict__ Hh, const float* __restrict__ b2,
                          float* __restrict__ out, int n) {
    int warp = (blockIdx.x * blockDim.x + threadIdx.x) >> 5;
    int lane = threadIdx.x & 31;
    if (warp >= n) return;
    float ax, ay, az, aw;
    agg_core((const uint2*)Hh, warp, lane, ax, ay, az, aw);

    float u2v = g_u2[warp];
    float u1v = g_u1[warp];
    float4 c1 = ((const float4*)g_c1)[lane];
    float4 c2 = ((const float4*)g_c2)[lane];
    float4 bb = ((const float4*)b2)[lane];

    float4 o;
    o.x = ax + u2v * c1.x + u1v * c2.x + bb.x;
    o.y = ay + u2v * c1.y + u1v * c2.y + bb.y;
    o.z = az + u2v * c1.z + u1v * c2.z + bb.z;
    o.w = aw + u2v * c1.w + u1v * c2.w + bb.w;
    ((float4*)out)[(size_t)warp * 32 + lane] = o;
}

// ---------------- launch: fork preproc onto side stream, overlap with GEMM branch ----------------
extern "C" void kernel_launch(void* const* d_in, const int* in_sizes, int n_in,
                              void* d_out, int out_size) {
    const float* feat = (const float*)d_in[0];
    const int*   ei   = (const int*)d_in[1];
    const float* W0 = (const float*)d_in[2];
    const float* b0 = (const float*)d_in[3];
    const float* W1 = (const float*)d_in[4];
    const float* b1 = (const float*)d_in[5];
    const float* W2 = (const float*)d_in[6];
    const float* b2 = (const float*)d_in[7];

    int n = in_sizes[0] / D;
    int e = in_sizes[1] / 2;
    if (n > NMAX) n = NMAX;
    if (e > EMAX) e = EMAX;
    const int* src = ei;
    const int* dstp = ei + e;

    __half *Hp, *Ap;
    float *Wtp, *W012p;
    cudaGetSymbolAddress((void**)&Hp, g_H);
    cudaGetSymbolAddress((void**)&Ap, g_A);
    cudaGetSymbolAddress((void**)&Wtp, g_Wt);
    cudaGetSymbolAddress((void**)&W012p, g_W012);

    // one-time side stream + events (created on first, non-captured, call)
    static cudaStream_t s_side = nullptr;
    static cudaEvent_t  s_fork = nullptr, s_join = nullptr;
    if (!s_side) {
        cudaStreamCreateWithFlags(&s_side, cudaStreamNonBlocking);
        cudaEventCreateWithFlags(&s_fork, cudaEventDisableTiming);
        cudaEventCreateWithFlags(&s_join, cudaEventDisableTiming);
    }

    int nb = (n + 1023) / 1024;
    int gm = (n + 127) / 128;
    int ga = (int)(((long long)n * 32 + 255) / 256);
    int gn = (n + 255) / 256;

    // fork: CSR build + scalar aggregations on side stream
    cudaEventRecord(s_fork, 0);
    cudaStreamWaitEvent(s_side, s_fork, 0);
    k_zero<<<gn, 256, 0, s_side>>>(n);
    k_count<<<(e + 255) / 256, 256, 0, s_side>>>(dstp, e);
    k_scan1<<<nb, 1024, 0, s_side>>>(n);
    k_scan3<<<nb, 1024, 0, s_side>>>(n, e);
    k_scatter<<<(e + 255) / 256, 256, 0, s_side>>>(src, dstp, e);
    k_aggs1<<<gn, 256, 0, s_side>>>(n);
    k_aggs2<<<gn, 256, 0, s_side>>>(n);
    cudaEventRecord(s_join, s_side);

    // main: collapsed weights + GEMM (independent of graph preprocessing)
    k_mm128<<<64, 256>>>(W0, W1, Wtp);
    k_mm128<<<64, 256>>>(Wtp, W2, W012p);
    k_cvec<<<1, 128>>>(b0, b1, W1, W2);
    k_gemm<<<gm, 256>>>(feat, W012p, Hp, n);

    // join: aggregations need both CSR and Y
    cudaStreamWaitEvent(0, s_join, 0);
    k_agg_mid<<<ga, 256>>>(Hp, Ap, n);
    k_agg_mid<<<ga, 256>>>(Ap, Hp, n);
    k_agg_fin<<<ga, 256>>>(Hp, b2, (float*)d_out, n);
}